// round 9
// baseline (speedup 1.0000x reference)
#include <cuda_runtime.h>

#define Sdim 4096
#define Ddim 64
#define WIN  256
#define Hn   16
#define TQ   64
#define CK   128
#define NCH  5
#define KBUF 640
#define SROW 644
#define QROW 68
#define NT   512

#define SM_QS   (TQ*SROW)             /* 41216 */
#define SM_KV   (SM_QS + Ddim*QROW)   /* 45568 */
#define SM_INV  (SM_KV + CK*Ddim)     /* 53760 */
#define SMEM_FLOATS (SM_INV + TQ)     /* 53824 floats = 215296 B */

typedef unsigned long long u64;

__device__ __forceinline__ u64 pk2(float v) {
    u64 r; asm("mov.b64 %0,{%1,%1};" : "=l"(r) : "f"(v)); return r;
}
__device__ __forceinline__ void fma2(u64 &d, u64 a, u64 b) {
    asm("fma.rn.f32x2 %0,%1,%2,%0;" : "+l"(d) : "l"(a), "l"(b));
}
__device__ __forceinline__ float2 upk2(u64 v) {
    float2 f; asm("mov.b64 {%0,%1},%2;" : "=f"(f.x), "=f"(f.y) : "l"(v)); return f;
}

#define SWZ(d) ((((d) >> 2) & 7) << 2)

__global__ __launch_bounds__(NT, 1)
void swa_kernel(const float* __restrict__ Q, const float* __restrict__ K,
                const float* __restrict__ V, float* __restrict__ outp,
                float* __restrict__ attn)
{
    extern __shared__ float sm[];
    float* scores = sm;                 // [64][SROW]
    float* Qs     = sm + SM_QS;         // [64][QROW] d-major, pre-scaled 0.125
    float* KV     = sm + SM_KV;         // K: [d][128] swizzled / V: [k][64]
    float* invs   = sm + SM_INV;        // [64]

    const int h    = blockIdx.y;
    const int qb   = blockIdx.x * TQ;
    const int tid  = threadIdx.x;
    const int koff = qb - WIN;          // buffer covers keys [koff, koff+640)
    const int goff = koff >> 2;         // group offset (koff divisible by 4)
    float* abase   = attn + (size_t)(h*Sdim + qb)*Sdim;

    // ---- Q load: transpose d-major, fold in 1/8 ----
    {
        const float4* Q4 = (const float4*)(Q + (size_t)(h*Sdim + qb)*Ddim);
        #pragma unroll
        for (int i = 0; i < 2; i++) {
            int idx = tid + NT*i;            // 1024 float4
            int q = idx >> 4, dg = idx & 15;
            float4 v = Q4[idx];
            Qs[(4*dg+0)*QROW + q] = v.x * 0.125f;
            Qs[(4*dg+1)*QROW + q] = v.y * 0.125f;
            Qs[(4*dg+2)*QROW + q] = v.z * 0.125f;
            Qs[(4*dg+3)*QROW + q] = v.w * 0.125f;
        }
    }

    const int warp = tid >> 5, lane = tid & 31;
    const int g1_q0 = warp << 2;            // warp owns 4 q-rows
    const int g1_k0 = lane << 2;            // lane owns 4 k-cols

    // ======== GEMM1 + interleaved zero-stores of out-of-band attn ========
    for (int c = 0; c < NCH; c++) {
        // ---- background zero writes: 26 float4 groups per thread per chunk ----
        {
            const float4 z = make_float4(0.f,0.f,0.f,0.f);
            #pragma unroll 2
            for (int i = 0; i < 26; i++) {
                int idx = tid + NT*(c*26 + i);          // covers 65536 groups
                if (idx < TQ*(Sdim/4)) {
                    int q = idx >> 10, g = idx & 1023;
                    if ((unsigned)(g - goff) >= 160u)   // not in band buffer
                        __stcs((float4*)(abase + ((size_t)q << 12) + (g << 2)), z);
                }
            }
        }
        const int kc = koff + c*CK;
        if (kc >= Sdim || kc + CK <= 0) {   // uniform: fully OOB
            float4 mneg = make_float4(-1e9f,-1e9f,-1e9f,-1e9f);
            #pragma unroll
            for (int j = 0; j < 4; j++)
                *(float4*)&scores[(g1_q0+j)*SROW + c*CK + g1_k0] = mneg;
            continue;
        }
        __syncthreads();                    // KV free (prev readers done)
        #pragma unroll
        for (int i = 0; i < 4; i++) {       // K chunk -> transposed swizzled
            int idx = tid + NT*i;           // 2048 float4
            int kk = idx >> 4, dg = idx & 15;
            int kg = kc + kk;
            float4 v = make_float4(0.f,0.f,0.f,0.f);
            if ((unsigned)kg < Sdim)
                v = *(const float4*)(K + (size_t)(h*Sdim + kg)*Ddim + 4*dg);
            int kk4 = kk & ~3, kr = kk & 3, d0 = 4*dg;
            KV[((d0+0)<<7) + ((kk4 ^ SWZ(d0+0)) | kr)] = v.x;
            KV[((d0+1)<<7) + ((kk4 ^ SWZ(d0+1)) | kr)] = v.y;
            KV[((d0+2)<<7) + ((kk4 ^ SWZ(d0+2)) | kr)] = v.z;
            KV[((d0+3)<<7) + ((kk4 ^ SWZ(d0+3)) | kr)] = v.w;
        }
        __syncthreads();

        u64 acc[4][2];
        #pragma unroll
        for (int j = 0; j < 4; j++) { acc[j][0] = 0ULL; acc[j][1] = 0ULL; }

        #pragma unroll 8
        for (int d = 0; d < Ddim; d++) {
            float4 qv = *(const float4*)(Qs + d*QROW + g1_q0);   // broadcast
            ulonglong2 kv = *(const ulonglong2*)(KV + (d<<7) + (g1_k0 ^ SWZ(d)));
            u64 a;
            a = pk2(qv.x); fma2(acc[0][0], a, kv.x); fma2(acc[0][1], a, kv.y);
            a = pk2(qv.y); fma2(acc[1][0], a, kv.x); fma2(acc[1][1], a, kv.y);
            a = pk2(qv.z); fma2(acc[2][0], a, kv.x); fma2(acc[2][1], a, kv.y);
            a = pk2(qv.w); fma2(acc[3][0], a, kv.x); fma2(acc[3][1], a, kv.y);
        }

        const int kg0 = kc + g1_k0;
        #pragma unroll
        for (int j = 0; j < 4; j++) {
            int qg = qb + g1_q0 + j;
            float2 a0 = upk2(acc[j][0]), a1 = upk2(acc[j][1]);
            float4 r;
            r.x = ((unsigned)(kg0+0) < Sdim && (unsigned)(kg0+0 - qg + WIN) <= 2u*WIN) ? a0.x : -1e9f;
            r.y = ((unsigned)(kg0+1) < Sdim && (unsigned)(kg0+1 - qg + WIN) <= 2u*WIN) ? a0.y : -1e9f;
            r.z = ((unsigned)(kg0+2) < Sdim && (unsigned)(kg0+2 - qg + WIN) <= 2u*WIN) ? a1.x : -1e9f;
            r.w = ((unsigned)(kg0+3) < Sdim && (unsigned)(kg0+3 - qg + WIN) <= 2u*WIN) ? a1.y : -1e9f;
            *(float4*)&scores[(g1_q0+j)*SROW + c*CK + g1_k0] = r;
        }
    }
    __syncthreads();

    // ======== softmax + fused band attn write: warp w owns rows 4w..4w+3 ====
    #pragma unroll
    for (int r = 0; r < 4; r++) {
        const int q = warp*4 + r;
        float* row = scores + q*SROW;
        float4 vals[5];
        float m = -3.0e38f;
        #pragma unroll
        for (int it = 0; it < 5; it++) {
            vals[it] = *(const float4*)(row + ((it*32 + lane) << 2));
            m = fmaxf(m, fmaxf(fmaxf(vals[it].x, vals[it].y), fmaxf(vals[it].z, vals[it].w)));
        }
        #pragma unroll
        for (int o = 16; o > 0; o >>= 1) m = fmaxf(m, __shfl_xor_sync(~0u, m, o));
        float s = 0.f;
        #pragma unroll
        for (int it = 0; it < 5; it++) {
            float4 v = vals[it];
            v.x = __expf(v.x - m); v.y = __expf(v.y - m);
            v.z = __expf(v.z - m); v.w = __expf(v.w - m);
            s += (v.x + v.y) + (v.z + v.w);
            vals[it] = v;                                    // FIX: keep exp'd copy
            *(float4*)(row + ((it*32 + lane) << 2)) = v;
        }
        #pragma unroll
        for (int o = 16; o > 0; o >>= 1) s += __shfl_xor_sync(~0u, s, o);
        float iv = 1.0f / s;
        if (lane == 0) invs[q] = iv;
        // band attn write for this row: 160 groups over 32 lanes = 5 iters
        float* arow = abase + ((size_t)q << 12);
        #pragma unroll
        for (int it = 0; it < 5; it++) {
            int bg = it*32 + lane;                  // band group 0..159
            int g  = bg + goff;                     // global group
            if ((unsigned)g < 1024u) {
                float4 p = vals[it];
                __stcs((float4*)(arow + (g << 2)),
                       make_float4(p.x*iv, p.y*iv, p.z*iv, p.w*iv));
            }
        }
    }

    // ======== GEMM2: out = P V, k-split-2 ========
    const int ksp = tid >> 8;           // which k-half
    const int t   = tid & 255;
    const int q0  = (t >> 4) << 2;      // 0..60
    const int d0  = (t & 15) << 2;      // 0..60

    u64 acc[4][2];
    #pragma unroll
    for (int j = 0; j < 4; j++) { acc[j][0] = 0ULL; acc[j][1] = 0ULL; }

    for (int c = 0; c < NCH; c++) {
        const int kc = koff + c*CK;
        if (kc >= Sdim || kc + CK <= 0) continue;   // P exactly 0 there
        __syncthreads();                             // prev KV readers done
        #pragma unroll
        for (int i = 0; i < 4; i++) {               // V chunk [k][64]
            int idx = tid + NT*i;
            int kk = idx >> 4, dg = idx & 15;
            int kg = kc + kk;
            float4 v = make_float4(0.f,0.f,0.f,0.f);
            if ((unsigned)kg < Sdim)
                v = *(const float4*)(V + (size_t)(h*Sdim + kg)*Ddim + 4*dg);
            *(float4*)&KV[(kk << 6) + 4*dg] = v;
        }
        __syncthreads();

        const float* srow = scores + c*CK;
        #pragma unroll 4
        for (int kb = ksp*64; kb < ksp*64 + 64; kb += 4) {
            float4 p0 = *(const float4*)(srow + (q0+0)*SROW + kb);
            float4 p1 = *(const float4*)(srow + (q0+1)*SROW + kb);
            float4 p2 = *(const float4*)(srow + (q0+2)*SROW + kb);
            float4 p3 = *(const float4*)(srow + (q0+3)*SROW + kb);
            #pragma unroll
            for (int i = 0; i < 4; i++) {
                ulonglong2 vv = *(const ulonglong2*)(KV + ((kb+i) << 6) + d0);
                const float* pf0 = &p0.x; const float* pf1 = &p1.x;
                const float* pf2 = &p2.x; const float* pf3 = &p3.x;
                u64 a;
                a = pk2(pf0[i]); fma2(acc[0][0], a, vv.x); fma2(acc[0][1], a, vv.y);
                a = pk2(pf1[i]); fma2(acc[1][0], a, vv.x); fma2(acc[1][1], a, vv.y);
                a = pk2(pf2[i]); fma2(acc[2][0], a, vv.x); fma2(acc[2][1], a, vv.y);
                a = pk2(pf3[i]); fma2(acc[3][0], a, vv.x); fma2(acc[3][1], a, vv.y);
            }
        }
    }

    // ======== cross-half reduction + output ========
    __syncthreads();
    float* red = sm + SM_QS;            // 4096 floats (Qs dead)
    if (ksp == 1) {
        #pragma unroll
        for (int j = 0; j < 4; j++) {
            float2 f0 = upk2(acc[j][0]), f1 = upk2(acc[j][1]);
            *(float4*)&red[(t*4 + j)*4] = make_float4(f0.x, f0.y, f1.x, f1.y);
        }
    }
    __syncthreads();
    if (ksp == 0) {
        float* obase = outp + (size_t)(h*Sdim + qb)*Ddim;
        #pragma unroll
        for (int j = 0; j < 4; j++) {
            float2 f0 = upk2(acc[j][0]), f1 = upk2(acc[j][1]);
            float4 o = *(const float4*)&red[(t*4 + j)*4];
            float iv = invs[q0 + j];
            o.x = (o.x + f0.x) * iv;
            o.y = (o.y + f0.y) * iv;
            o.z = (o.z + f1.x) * iv;
            o.w = (o.w + f1.y) * iv;
            __stcs((float4*)(obase + (size_t)(q0 + j)*Ddim + d0), o);
        }
    }
}

extern "C" void kernel_launch(void* const* d_in, const int* in_sizes, int n_in,
                              void* d_out, int out_size) {
    const float* Q = (const float*)d_in[0];
    const float* K = (const float*)d_in[1];
    const float* V = (const float*)d_in[2];
    float* outp = (float*)d_out;
    float* attn = outp + (size_t)Hn*Sdim*Ddim;      // tuple: (out, attn)

    const int smem_bytes = SMEM_FLOATS * (int)sizeof(float);  // 215296
    cudaFuncSetAttribute(swa_kernel, cudaFuncAttributeMaxDynamicSharedMemorySize,
                         smem_bytes);
    dim3 grid(Sdim / TQ, Hn);                        // (64, 16)
    swa_kernel<<<grid, NT, smem_bytes>>>(Q, K, V, outp, attn);
}

// round 10
// speedup vs baseline: 1.0455x; 1.0455x over previous
#include <cuda_runtime.h>

#define Sdim 4096
#define Ddim 64
#define WIN  256
#define Hn   16
#define TQ   64
#define CK   128
#define NCH  5
#define KBUF 640
#define SROW 644
#define NT   512

#define SM_QS   (TQ*SROW)             /* 41216 */
#define SM_KV   (SM_QS + 64*64)       /* 45312 */
#define SM_INV  (SM_KV + CK*Ddim)     /* 53504 */
#define SMEM_FLOATS (SM_INV + TQ)     /* 53568 floats = 214272 B */

typedef unsigned long long u64;

__device__ __forceinline__ u64 pk2(float v) {
    u64 r; asm("mov.b64 %0,{%1,%1};" : "=l"(r) : "f"(v)); return r;
}
__device__ __forceinline__ void fma2(u64 &d, u64 a, u64 b) {
    asm("fma.rn.f32x2 %0,%1,%2,%0;" : "+l"(d) : "l"(a), "l"(b));
}
__device__ __forceinline__ float2 upk2(u64 v) {
    float2 f; asm("mov.b64 {%0,%1},%2;" : "=f"(f.x), "=f"(f.y) : "l"(v)); return f;
}

#define SWZ(d) ((((d) >> 2) & 7) << 2)

__global__ __launch_bounds__(NT, 1)
void swa_kernel(const float* __restrict__ Q, const float* __restrict__ K,
                const float* __restrict__ V, float* __restrict__ outp,
                float* __restrict__ attn)
{
    extern __shared__ float sm[];
    float* scores = sm;                 // [64][SROW]
    float* Qs     = sm + SM_QS;         // [64][64] d-major, pre-scaled 0.125
    float* KV     = sm + SM_KV;         // K: [d][128] swizzled / V: [k][64]
    float* invs   = sm + SM_INV;        // [64]

    const int h    = blockIdx.y;
    const int qb   = blockIdx.x * TQ;
    const int tid  = threadIdx.x;
    const int koff = qb - WIN;          // buffer covers keys [koff, koff+640)
    const int goff = koff >> 2;
    float* abase   = attn + (size_t)(h*Sdim + qb)*Sdim;

    // ---- Q load: q-fastest (coalesced LDG, conflict-free STS), fold in 1/8 ----
    {
        const float4* Q4 = (const float4*)(Q + (size_t)(h*Sdim + qb)*Ddim);
        #pragma unroll
        for (int i = 0; i < 2; i++) {
            int idx = tid + NT*i;            // 1024 float4
            int q = idx & 63, dg = idx >> 6; // dg in [0,16)
            float4 v = Q4[(size_t)q*16 + dg];
            Qs[(4*dg+0)*64 + q] = v.x * 0.125f;
            Qs[(4*dg+1)*64 + q] = v.y * 0.125f;
            Qs[(4*dg+2)*64 + q] = v.z * 0.125f;
            Qs[(4*dg+3)*64 + q] = v.w * 0.125f;
        }
    }

    const int warp = tid >> 5, lane = tid & 31;
    // GEMM1: 4x4 warp grid -> warp tile 16q x 32k; lane 4q-groups x 8k-groups
    const int g1_q0 = ((warp & 3) << 4) + ((lane >> 3) << 2);
    const int g1_k0 = ((warp >> 2) << 5) + ((lane & 7) << 2);

    // ======== GEMM1 + interleaved zero-stores of out-of-band attn ========
    for (int c = 0; c < NCH; c++) {
        {   // background zero writes
            const float4 z = make_float4(0.f,0.f,0.f,0.f);
            #pragma unroll 2
            for (int i = 0; i < 26; i++) {
                int idx = tid + NT*(c*26 + i);
                if (idx < TQ*(Sdim/4)) {
                    int q = idx >> 10, g = idx & 1023;
                    if ((unsigned)(g - goff) >= 160u)
                        __stcs((float4*)(abase + ((size_t)q << 12) + (g << 2)), z);
                }
            }
        }
        const int kc = koff + c*CK;
        if (kc >= Sdim || kc + CK <= 0) {   // uniform: fully OOB
            float4 mneg = make_float4(-1e9f,-1e9f,-1e9f,-1e9f);
            #pragma unroll
            for (int j = 0; j < 4; j++)
                *(float4*)&scores[(g1_q0+j)*SROW + c*CK + g1_k0] = mneg;
            continue;
        }
        __syncthreads();
        #pragma unroll
        for (int i = 0; i < 4; i++) {       // K chunk -> transposed swizzled
            int idx = tid + NT*i;
            int kk = idx >> 4, dg = idx & 15;
            int kg = kc + kk;
            float4 v = make_float4(0.f,0.f,0.f,0.f);
            if ((unsigned)kg < Sdim)
                v = *(const float4*)(K + (size_t)(h*Sdim + kg)*Ddim + 4*dg);
            int kk4 = kk & ~3, kr = kk & 3, d0 = 4*dg;
            KV[((d0+0)<<7) + ((kk4 ^ SWZ(d0+0)) | kr)] = v.x;
            KV[((d0+1)<<7) + ((kk4 ^ SWZ(d0+1)) | kr)] = v.y;
            KV[((d0+2)<<7) + ((kk4 ^ SWZ(d0+2)) | kr)] = v.z;
            KV[((d0+3)<<7) + ((kk4 ^ SWZ(d0+3)) | kr)] = v.w;
        }
        __syncthreads();

        u64 acc[4][2];
        #pragma unroll
        for (int j = 0; j < 4; j++) { acc[j][0] = 0ULL; acc[j][1] = 0ULL; }

        #pragma unroll 8
        for (int d = 0; d < Ddim; d++) {
            float4 qv = *(const float4*)(Qs + (d<<6) + g1_q0);             // 1 wf
            ulonglong2 kv = *(const ulonglong2*)(KV + (d<<7) + (g1_k0 ^ SWZ(d))); // 1 wf
            u64 a;
            a = pk2(qv.x); fma2(acc[0][0], a, kv.x); fma2(acc[0][1], a, kv.y);
            a = pk2(qv.y); fma2(acc[1][0], a, kv.x); fma2(acc[1][1], a, kv.y);
            a = pk2(qv.z); fma2(acc[2][0], a, kv.x); fma2(acc[2][1], a, kv.y);
            a = pk2(qv.w); fma2(acc[3][0], a, kv.x); fma2(acc[3][1], a, kv.y);
        }

        const int kg0 = kc + g1_k0;
        #pragma unroll
        for (int j = 0; j < 4; j++) {
            int qg = qb + g1_q0 + j;
            float2 a0 = upk2(acc[j][0]), a1 = upk2(acc[j][1]);
            float4 r;
            r.x = ((unsigned)(kg0+0) < Sdim && (unsigned)(kg0+0 - qg + WIN) <= 2u*WIN) ? a0.x : -1e9f;
            r.y = ((unsigned)(kg0+1) < Sdim && (unsigned)(kg0+1 - qg + WIN) <= 2u*WIN) ? a0.y : -1e9f;
            r.z = ((unsigned)(kg0+2) < Sdim && (unsigned)(kg0+2 - qg + WIN) <= 2u*WIN) ? a1.x : -1e9f;
            r.w = ((unsigned)(kg0+3) < Sdim && (unsigned)(kg0+3 - qg + WIN) <= 2u*WIN) ? a1.y : -1e9f;
            *(float4*)&scores[(g1_q0+j)*SROW + c*CK + g1_k0] = r;
        }
    }
    __syncthreads();

    // ======== softmax + fused band attn write: warp w owns rows 4w..4w+3 ====
    #pragma unroll
    for (int r = 0; r < 4; r++) {
        const int q = warp*4 + r;
        float* row = scores + q*SROW;
        float4 vals[5];
        float m = -3.0e38f;
        #pragma unroll
        for (int it = 0; it < 5; it++) {
            vals[it] = *(const float4*)(row + ((it*32 + lane) << 2));
            m = fmaxf(m, fmaxf(fmaxf(vals[it].x, vals[it].y), fmaxf(vals[it].z, vals[it].w)));
        }
        #pragma unroll
        for (int o = 16; o > 0; o >>= 1) m = fmaxf(m, __shfl_xor_sync(~0u, m, o));
        float s = 0.f;
        #pragma unroll
        for (int it = 0; it < 5; it++) {
            float4 v = vals[it];
            v.x = __expf(v.x - m); v.y = __expf(v.y - m);
            v.z = __expf(v.z - m); v.w = __expf(v.w - m);
            s += (v.x + v.y) + (v.z + v.w);
            vals[it] = v;
            *(float4*)(row + ((it*32 + lane) << 2)) = v;
        }
        #pragma unroll
        for (int o = 16; o > 0; o >>= 1) s += __shfl_xor_sync(~0u, s, o);
        float iv = 1.0f / s;
        if (lane == 0) invs[q] = iv;
        float* arow = abase + ((size_t)q << 12);
        #pragma unroll
        for (int it = 0; it < 5; it++) {
            int g = it*32 + lane + goff;
            if ((unsigned)g < 1024u) {
                float4 p = vals[it];
                __stcs((float4*)(arow + (g << 2)),
                       make_float4(p.x*iv, p.y*iv, p.z*iv, p.w*iv));
            }
        }
    }

    // ======== GEMM2: out = P V, k-split-2 ========
    const int ksp = tid >> 8;
    const int t   = tid & 255;
    const int q0  = (t >> 4) << 2;
    const int d0  = (t & 15) << 2;

    u64 acc[4][2];
    #pragma unroll
    for (int j = 0; j < 4; j++) { acc[j][0] = 0ULL; acc[j][1] = 0ULL; }

    for (int c = 0; c < NCH; c++) {
        const int kc = koff + c*CK;
        if (kc >= Sdim || kc + CK <= 0) continue;
        __syncthreads();
        #pragma unroll
        for (int i = 0; i < 4; i++) {       // V chunk [k][64]
            int idx = tid + NT*i;
            int kk = idx >> 4, dg = idx & 15;
            int kg = kc + kk;
            float4 v = make_float4(0.f,0.f,0.f,0.f);
            if ((unsigned)kg < Sdim)
                v = *(const float4*)(V + (size_t)(h*Sdim + kg)*Ddim + 4*dg);
            *(float4*)&KV[(kk << 6) + 4*dg] = v;
        }
        __syncthreads();

        const float* srow = scores + c*CK;
        #pragma unroll 4
        for (int kb = ksp*64; kb < ksp*64 + 64; kb += 4) {
            float4 p0 = *(const float4*)(srow + (q0+0)*SROW + kb);
            float4 p1 = *(const float4*)(srow + (q0+1)*SROW + kb);
            float4 p2 = *(const float4*)(srow + (q0+2)*SROW + kb);
            float4 p3 = *(const float4*)(srow + (q0+3)*SROW + kb);
            #pragma unroll
            for (int i = 0; i < 4; i++) {
                ulonglong2 vv = *(const ulonglong2*)(KV + ((kb+i) << 6) + d0);
                const float* pf0 = &p0.x; const float* pf1 = &p1.x;
                const float* pf2 = &p2.x; const float* pf3 = &p3.x;
                u64 a;
                a = pk2(pf0[i]); fma2(acc[0][0], a, vv.x); fma2(acc[0][1], a, vv.y);
                a = pk2(pf1[i]); fma2(acc[1][0], a, vv.x); fma2(acc[1][1], a, vv.y);
                a = pk2(pf2[i]); fma2(acc[2][0], a, vv.x); fma2(acc[2][1], a, vv.y);
                a = pk2(pf3[i]); fma2(acc[3][0], a, vv.x); fma2(acc[3][1], a, vv.y);
            }
        }
    }

    // ======== cross-half reduction + output ========
    __syncthreads();
    float* red = sm + SM_QS;            // 4096 floats (Qs dead)
    if (ksp == 1) {
        #pragma unroll
        for (int j = 0; j < 4; j++) {
            float2 f0 = upk2(acc[j][0]), f1 = upk2(acc[j][1]);
            *(float4*)&red[(t*4 + j)*4] = make_float4(f0.x, f0.y, f1.x, f1.y);
        }
    }
    __syncthreads();
    if (ksp == 0) {
        float* obase = outp + (size_t)(h*Sdim + qb)*Ddim;
        #pragma unroll
        for (int j = 0; j < 4; j++) {
            float2 f0 = upk2(acc[j][0]), f1 = upk2(acc[j][1]);
            float4 o = *(const float4*)&red[(t*4 + j)*4];
            float iv = invs[q0 + j];
            o.x = (o.x + f0.x) * iv;
            o.y = (o.y + f0.y) * iv;
            o.z = (o.z + f1.x) * iv;
            o.w = (o.w + f1.y) * iv;
            __stcs((float4*)(obase + (size_t)(q0 + j)*Ddim + d0), o);
        }
    }
}

extern "C" void kernel_launch(void* const* d_in, const int* in_sizes, int n_in,
                              void* d_out, int out_size) {
    const float* Q = (const float*)d_in[0];
    const float* K = (const float*)d_in[1];
    const float* V = (const float*)d_in[2];
    float* outp = (float*)d_out;
    float* attn = outp + (size_t)Hn*Sdim*Ddim;

    const int smem_bytes = SMEM_FLOATS * (int)sizeof(float);  // 214272
    cudaFuncSetAttribute(swa_kernel, cudaFuncAttributeMaxDynamicSharedMemorySize,
                         smem_bytes);
    dim3 grid(Sdim / TQ, Hn);                        // (64, 16)
    swa_kernel<<<grid, NT, smem_bytes>>>(Q, K, V, outp, attn);
}

// round 11
// speedup vs baseline: 1.1238x; 1.0749x over previous
#include <cuda_runtime.h>

#define Sdim 4096
#define Ddim 64
#define WIN  256
#define Hn   16
#define TQ   32
#define CK   64
#define NCH  9
#define KBUF 576
#define SROW 580
#define NT   256
#define KSTR 66
#define VSTR 68

#define SM_QS   (TQ*SROW)              /* 18560 */
#define SM_KV   (SM_QS + 2048)         /* 20608 */
#define SM_INV  (SM_KV + CK*VSTR)      /* 24960 */
#define SMEM_FLOATS (SM_INV + TQ)      /* 24992 floats = 99968 B */

typedef unsigned long long u64;

__device__ __forceinline__ u64 pk2(float v) {
    u64 r; asm("mov.b64 %0,{%1,%1};" : "=l"(r) : "f"(v)); return r;
}
__device__ __forceinline__ void fma2(u64 &d, u64 a, u64 b) {
    asm("fma.rn.f32x2 %0,%1,%2,%0;" : "+l"(d) : "l"(a), "l"(b));
}
__device__ __forceinline__ float2 upk2(u64 v) {
    float2 f; asm("mov.b64 {%0,%1},%2;" : "=f"(f.x), "=f"(f.y) : "l"(v)); return f;
}

__global__ __launch_bounds__(NT, 2)
void swa_kernel(const float* __restrict__ Q, const float* __restrict__ K,
                const float* __restrict__ V, float* __restrict__ outp,
                float* __restrict__ attn)
{
    extern __shared__ float sm[];
    float* scores = sm;                 // [32][SROW]
    float* Qs     = sm + SM_QS;         // [64][32] d-major, pre-scaled 0.125
    float* KV     = sm + SM_KV;         // K: [d][KSTR] / V: [k][VSTR]
    float* invs   = sm + SM_INV;        // [32]

    const int h    = blockIdx.y;
    const int qb   = blockIdx.x * TQ;
    const int tid  = threadIdx.x;
    const int koff = qb - WIN;          // buffer keys [koff, koff+576)
    const int goff = koff >> 2;
    float* abase   = attn + (size_t)(h*Sdim + qb)*Sdim;
    const int warp = tid >> 5, lane = tid & 31;

    const float4* Q4 = (const float4*)(Q + (size_t)(h*Sdim + qb)*Ddim);
    const float4* K4 = (const float4*)(K + (size_t)h*Sdim*Ddim);
    const float4* V4 = (const float4*)(V + (size_t)h*Sdim*Ddim);
    const float4 fzero = make_float4(0.f,0.f,0.f,0.f);

    // ---- Q load + transpose (warp w -> d cols 8w..8w+7), conflict-free STS ----
    {
        float4 a = Q4[lane*16 + warp*2];
        float4 b = Q4[lane*16 + warp*2 + 1];
        int d0 = warp*8;
        Qs[(d0+0)*32 + lane] = a.x*0.125f;
        Qs[(d0+1)*32 + lane] = a.y*0.125f;
        Qs[(d0+2)*32 + lane] = a.z*0.125f;
        Qs[(d0+3)*32 + lane] = a.w*0.125f;
        Qs[(d0+4)*32 + lane] = b.x*0.125f;
        Qs[(d0+5)*32 + lane] = b.y*0.125f;
        Qs[(d0+6)*32 + lane] = b.z*0.125f;
        Qs[(d0+7)*32 + lane] = b.w*0.125f;
    }

    // ---- zero-fill attn outside band: warp w owns rows 4w..4w+3 ----
    {
        int lo = max(0, goff), hi = min(1024, goff + KBUF/4);
        #pragma unroll
        for (int r = 0; r < 4; r++) {
            float4* arow = (float4*)(abase + ((size_t)(warp*4 + r) << 12));
            for (int g = lane; g < lo; g += 32) __stcs(arow + g, fzero);
            for (int g = hi + lane; g < 1024; g += 32) __stcs(arow + g, fzero);
        }
    }

    const int c0 = (koff < 0) ? ((-koff) >> 6) : 0;
    const int c1 = min(NCH-1, (Sdim-1-koff) >> 6);

    // GEMM1 mapping: warp grid 2q x 4k; warp tile 16q x 16k; lane tile 4q x 2k
    const int g1q = ((warp & 1) << 4) + ((lane >> 3) << 2);
    const int g1k = ((warp >> 1) << 4) + ((lane & 7) << 1);

    // fill scores of invalid chunks with -1e9
    for (int c = 0; c < c0; c++) {
        #pragma unroll
        for (int j = 0; j < 4; j++)
            *(float2*)&scores[(g1q+j)*SROW + c*CK + g1k] = make_float2(-1e9f,-1e9f);
    }
    for (int c = c1+1; c < NCH; c++) {
        #pragma unroll
        for (int j = 0; j < 4; j++)
            *(float2*)&scores[(g1q+j)*SROW + c*CK + g1k] = make_float2(-1e9f,-1e9f);
    }
    __syncthreads();   // Qs ready

    // ======== GEMM1 pipeline with register K-prefetch ========
    {
        float4 kreg[4];
        {   // prefetch chunk c0
            int kc = koff + c0*CK;
            #pragma unroll
            for (int i = 0; i < 4; i++) {
                int idx = tid + NT*i;
                int kg = kc + (idx >> 4);
                kreg[i] = ((unsigned)kg < Sdim) ? K4[(size_t)kg*16 + (idx & 15)] : fzero;
            }
        }
        for (int c = c0; c <= c1; c++) {
            __syncthreads();            // KV free
            #pragma unroll
            for (int i = 0; i < 4; i++) {   // STS transpose K -> [d][KSTR]
                int idx = tid + NT*i;
                int kk = idx >> 4, dg = idx & 15, d0 = 4*dg;
                KV[(d0+0)*KSTR + kk] = kreg[i].x;
                KV[(d0+1)*KSTR + kk] = kreg[i].y;
                KV[(d0+2)*KSTR + kk] = kreg[i].z;
                KV[(d0+3)*KSTR + kk] = kreg[i].w;
            }
            __syncthreads();
            if (c < c1) {               // prefetch next (latency hidden by compute)
                int kc = koff + (c+1)*CK;
                #pragma unroll
                for (int i = 0; i < 4; i++) {
                    int idx = tid + NT*i;
                    int kg = kc + (idx >> 4);
                    kreg[i] = ((unsigned)kg < Sdim) ? K4[(size_t)kg*16 + (idx & 15)] : fzero;
                }
            }
            u64 acc[4] = {0ULL,0ULL,0ULL,0ULL};
            #pragma unroll 16
            for (int d = 0; d < Ddim; d++) {
                float4 qv = *(const float4*)(Qs + d*32 + g1q);
                u64 kv = *(const u64*)(KV + d*KSTR + g1k);
                fma2(acc[0], pk2(qv.x), kv);
                fma2(acc[1], pk2(qv.y), kv);
                fma2(acc[2], pk2(qv.z), kv);
                fma2(acc[3], pk2(qv.w), kv);
            }
            const int kg0 = koff + c*CK + g1k;
            #pragma unroll
            for (int j = 0; j < 4; j++) {
                int qg = qb + g1q + j;
                float2 a = upk2(acc[j]);
                float2 r;
                r.x = ((unsigned)kg0     < Sdim && (unsigned)(kg0   - qg + WIN) <= 2u*WIN) ? a.x : -1e9f;
                r.y = ((unsigned)(kg0+1) < Sdim && (unsigned)(kg0+1 - qg + WIN) <= 2u*WIN) ? a.y : -1e9f;
                *(float2*)&scores[(g1q+j)*SROW + c*CK + g1k] = r;
            }
        }
    }
    __syncthreads();

    // ======== softmax + fused band attn write: warp w owns rows 4w..4w+3 ====
    #pragma unroll
    for (int r = 0; r < 4; r++) {
        const int q = warp*4 + r;
        float* row = scores + q*SROW;
        float4 vals[5];
        float m = -3.0e38f;
        #pragma unroll
        for (int it = 0; it < 5; it++) {
            int g = it*32 + lane;
            vals[it] = (g < 144) ? *(const float4*)(row + (g << 2))
                                 : make_float4(-1e9f,-1e9f,-1e9f,-1e9f);
            m = fmaxf(m, fmaxf(fmaxf(vals[it].x, vals[it].y), fmaxf(vals[it].z, vals[it].w)));
        }
        #pragma unroll
        for (int o = 16; o > 0; o >>= 1) m = fmaxf(m, __shfl_xor_sync(~0u, m, o));
        float s = 0.f;
        #pragma unroll
        for (int it = 0; it < 5; it++) {
            float4 v = vals[it];
            v.x = __expf(v.x - m); v.y = __expf(v.y - m);
            v.z = __expf(v.z - m); v.w = __expf(v.w - m);
            s += (v.x + v.y) + (v.z + v.w);
            vals[it] = v;
            int g = it*32 + lane;
            if (g < 144) *(float4*)(row + (g << 2)) = v;
        }
        #pragma unroll
        for (int o = 16; o > 0; o >>= 1) s += __shfl_xor_sync(~0u, s, o);
        float iv = 1.0f / s;
        if (lane == 0) invs[q] = iv;
        float* arow = abase + ((size_t)q << 12);
        #pragma unroll
        for (int it = 0; it < 5; it++) {
            int bg = it*32 + lane;
            int g  = bg + goff;
            if (bg < 144 && (unsigned)g < 1024u) {
                float4 p = vals[it];
                __stcs((float4*)(arow + (g << 2)),
                       make_float4(p.x*iv, p.y*iv, p.z*iv, p.w*iv));
            }
        }
    }

    // ======== GEMM2: out = P V, k-split-2, register V-prefetch ========
    const int ksp = tid >> 7;
    const int t   = tid & 127;
    const int q0  = (t >> 4) << 2;      // 0..28
    const int d0  = (t & 15) << 2;      // 0..60

    u64 acc2[4][2];
    #pragma unroll
    for (int j = 0; j < 4; j++) { acc2[j][0] = 0ULL; acc2[j][1] = 0ULL; }

    {
        float4 vreg[4];
        {   // prefetch chunk c0
            int kc = koff + c0*CK;
            #pragma unroll
            for (int i = 0; i < 4; i++) {
                int idx = tid + NT*i;
                int kg = kc + (idx >> 4);
                vreg[i] = ((unsigned)kg < Sdim) ? V4[(size_t)kg*16 + (idx & 15)] : fzero;
            }
        }
        for (int c = c0; c <= c1; c++) {
            __syncthreads();            // prev KV readers done / P ready (1st iter)
            #pragma unroll
            for (int i = 0; i < 4; i++) {
                int idx = tid + NT*i;
                int kk = idx >> 4, dg = idx & 15;
                *(float4*)&KV[kk*VSTR + 4*dg] = vreg[i];
            }
            __syncthreads();
            if (c < c1) {
                int kc = koff + (c+1)*CK;
                #pragma unroll
                for (int i = 0; i < 4; i++) {
                    int idx = tid + NT*i;
                    int kg = kc + (idx >> 4);
                    vreg[i] = ((unsigned)kg < Sdim) ? V4[(size_t)kg*16 + (idx & 15)] : fzero;
                }
            }
            const float* srow = scores + c*CK;
            #pragma unroll
            for (int kb = 0; kb < 32; kb += 4) {
                int kbs = ksp*32 + kb;
                float4 p0 = *(const float4*)(srow + (q0+0)*SROW + kbs);
                float4 p1 = *(const float4*)(srow + (q0+1)*SROW + kbs);
                float4 p2 = *(const float4*)(srow + (q0+2)*SROW + kbs);
                float4 p3 = *(const float4*)(srow + (q0+3)*SROW + kbs);
                #pragma unroll
                for (int i = 0; i < 4; i++) {
                    ulonglong2 vv = *(const ulonglong2*)(KV + (kbs+i)*VSTR + d0);
                    const float* f0 = &p0.x; const float* f1 = &p1.x;
                    const float* f2 = &p2.x; const float* f3 = &p3.x;
                    u64 a;
                    a = pk2(f0[i]); fma2(acc2[0][0], a, vv.x); fma2(acc2[0][1], a, vv.y);
                    a = pk2(f1[i]); fma2(acc2[1][0], a, vv.x); fma2(acc2[1][1], a, vv.y);
                    a = pk2(f2[i]); fma2(acc2[2][0], a, vv.x); fma2(acc2[2][1], a, vv.y);
                    a = pk2(f3[i]); fma2(acc2[3][0], a, vv.x); fma2(acc2[3][1], a, vv.y);
                }
            }
        }
    }

    // ======== cross-half reduction + output ========
    __syncthreads();
    float* red = sm;                    // scores dead; 2048 floats
    if (ksp == 1) {
        #pragma unroll
        for (int j = 0; j < 4; j++) {
            float2 f0 = upk2(acc2[j][0]), f1 = upk2(acc2[j][1]);
            *(float4*)&red[j*512 + t*4] = make_float4(f0.x, f0.y, f1.x, f1.y);
        }
    }
    __syncthreads();
    if (ksp == 0) {
        float* obase = outp + (size_t)(h*Sdim + qb)*Ddim;
        #pragma unroll
        for (int j = 0; j < 4; j++) {
            float2 f0 = upk2(acc2[j][0]), f1 = upk2(acc2[j][1]);
            float4 o = *(const float4*)&red[j*512 + t*4];
            float iv = invs[q0 + j];
            o.x = (o.x + f0.x) * iv;
            o.y = (o.y + f0.y) * iv;
            o.z = (o.z + f1.x) * iv;
            o.w = (o.w + f1.y) * iv;
            __stcs((float4*)(obase + (size_t)(q0 + j)*Ddim + d0), o);
        }
    }
}

extern "C" void kernel_launch(void* const* d_in, const int* in_sizes, int n_in,
                              void* d_out, int out_size) {
    const float* Q = (const float*)d_in[0];
    const float* K = (const float*)d_in[1];
    const float* V = (const float*)d_in[2];
    float* outp = (float*)d_out;
    float* attn = outp + (size_t)Hn*Sdim*Ddim;

    const int smem_bytes = SMEM_FLOATS * (int)sizeof(float);  // 99968
    cudaFuncSetAttribute(swa_kernel, cudaFuncAttributeMaxDynamicSharedMemorySize,
                         smem_bytes);
    dim3 grid(Sdim / TQ, Hn);                        // (128, 16)
    swa_kernel<<<grid, NT, smem_bytes>>>(Q, K, V, outp, attn);
}